// round 2
// baseline (speedup 1.0000x reference)
#include <cuda_runtime.h>
#include <cuda_bf16.h>

// Problem shapes (fixed by the dataset's setup_inputs)
#define B_  64
#define T_  262144
#define C_  3
#define K_  16384
#define H_  32

// pooled column sums from a register array f[20] holding the 5 aligned float4
// chunks; S is a compile-time shift (0..3) so all indices are constants and
// f[] stays in registers.
#define POOL3(S)                                                             \
    p0 = f[(S)+0] + f[(S)+3] + f[(S)+6] + f[(S)+9]  + f[(S)+12];             \
    p1 = f[(S)+1] + f[(S)+4] + f[(S)+7] + f[(S)+10] + f[(S)+13];             \
    p2 = f[(S)+2] + f[(S)+5] + f[(S)+8] + f[(S)+11] + f[(S)+14];

__global__ __launch_bounds__(256) void refiner_kernel(
    const float* __restrict__ x,          // [B, T, C]
    const int*   __restrict__ ids,        // [B, K] int32 (JAX x64 disabled!)
    const float* __restrict__ W1,         // [C, H]
    const float* __restrict__ b1,         // [H]
    const float* __restrict__ W2,         // [H, 1]
    const float* __restrict__ b2,         // [1]
    float* __restrict__ out)              // [B, K]
{
    __shared__ __align__(16) float sW1[C_ * H_];  // rows c=0,1,2 of 32
    __shared__ __align__(16) float sB1[H_];
    __shared__ __align__(16) float sW2[H_];
    __shared__ float sB2;

    const int tid = threadIdx.x;
    if (tid < 96)                 sW1[tid]       = W1[tid];
    else if (tid < 128)           sB1[tid - 96]  = b1[tid - 96];
    else if (tid < 160)           sW2[tid - 128] = W2[tid - 128];
    else if (tid == 160)          sB2            = b2[0];
    __syncthreads();

    const int gid = blockIdx.x * 256 + tid;       // 0 .. B*K-1
    const int b   = gid >> 14;                    // gid / K_
    const int id  = ids[gid];
    const float* xb = x + (size_t)b * ((size_t)T_ * C_);

    float p0, p1, p2;

    if (id >= 2 && id <= T_ - 7) {
        // Fast path: full 5-row interior window; 5 aligned float4 loads
        // covering bytes [12*(id-2), 12*(id-2)+60) (plus <=12B of slack).
        const size_t f0 = (size_t)(id - 2) * 3;        // first float index
        const int    sh = (int)(f0 & 3);
        const float4* p4 = reinterpret_cast<const float4*>(xb + (f0 & ~(size_t)3));
        float4 c0 = p4[0], c1 = p4[1], c2 = p4[2], c3 = p4[3], c4 = p4[4];
        float f[20] = { c0.x, c0.y, c0.z, c0.w,
                        c1.x, c1.y, c1.z, c1.w,
                        c2.x, c2.y, c2.z, c2.w,
                        c3.x, c3.y, c3.z, c3.w,
                        c4.x, c4.y, c4.z, c4.w };
        switch (sh) {
            case 0:  { POOL3(0) } break;
            case 1:  { POOL3(1) } break;
            case 2:  { POOL3(2) } break;
            default: { POOL3(3) } break;
        }
        const float inv5 = 1.0f / 5.0f;
        p0 *= inv5; p1 *= inv5; p2 *= inv5;
    } else {
        // Slow path (edge ids, ~9/262144 probability): scalar masked mean.
        float s0 = 0.f, s1 = 0.f, s2 = 0.f, cnt = 0.f;
        #pragma unroll
        for (int o = -2; o <= 2; o++) {
            int pos = id + o;
            if (pos >= 0 && pos < T_) {
                const float* r = xb + (size_t)pos * 3;
                s0 += r[0]; s1 += r[1]; s2 += r[2]; cnt += 1.0f;
            }
        }
        const float inv = 1.0f / cnt;
        p0 = s0 * inv; p1 = s1 * inv; p2 = s2 * inv;
    }

    // MLP: h = relu(pooled @ W1 + b1); out = h @ W2 + b2.
    // Broadcast float4 LDS reads of the shared weight tiles.
    float acc = sB2;
    const float4* wA = reinterpret_cast<const float4*>(sW1);          // c=0
    const float4* wB = reinterpret_cast<const float4*>(sW1 + 32);     // c=1
    const float4* wC = reinterpret_cast<const float4*>(sW1 + 64);     // c=2
    const float4* vb = reinterpret_cast<const float4*>(sB1);
    const float4* v2 = reinterpret_cast<const float4*>(sW2);
    #pragma unroll
    for (int j = 0; j < H_ / 4; j++) {
        float4 a  = wA[j], bb = wB[j], cc = wC[j], dd = vb[j], ee = v2[j];
        float h;
        h = fmaf(p0, a.x, fmaf(p1, bb.x, fmaf(p2, cc.x, dd.x)));
        acc = fmaf(fmaxf(h, 0.f), ee.x, acc);
        h = fmaf(p0, a.y, fmaf(p1, bb.y, fmaf(p2, cc.y, dd.y)));
        acc = fmaf(fmaxf(h, 0.f), ee.y, acc);
        h = fmaf(p0, a.z, fmaf(p1, bb.z, fmaf(p2, cc.z, dd.z)));
        acc = fmaf(fmaxf(h, 0.f), ee.z, acc);
        h = fmaf(p0, a.w, fmaf(p1, bb.w, fmaf(p2, cc.w, dd.w)));
        acc = fmaf(fmaxf(h, 0.f), ee.w, acc);
    }

    out[gid] = acc;
}

extern "C" void kernel_launch(void* const* d_in, const int* in_sizes, int n_in,
                              void* d_out, int out_size) {
    const float* x   = (const float*)d_in[0];
    const int*   ids = (const int*)d_in[1];
    const float* W1  = (const float*)d_in[2];
    const float* b1  = (const float*)d_in[3];
    const float* W2  = (const float*)d_in[4];
    const float* b2  = (const float*)d_in[5];
    float*       out = (float*)d_out;

    const int total = out_size;           // B*K = 1048576
    const int block = 256;
    const int grid  = (total + block - 1) / block;
    refiner_kernel<<<grid, block>>>(x, ids, W1, b1, W2, b2, out);
}

// round 3
// speedup vs baseline: 1.0021x; 1.0021x over previous
#include <cuda_runtime.h>
#include <cuda_bf16.h>

#define B_  64
#define T_  262144
#define C_  3
#define K_  16384
#define H_  32

// Pool the 5-row window (15 floats starting at compile-time shift S inside the
// 20-float register block f[]) into per-column sums p0,p1,p2.
#define POOL3(f, S, p0, p1, p2)                                              \
    p0 = f[(S)+0] + f[(S)+3] + f[(S)+6] + f[(S)+9]  + f[(S)+12];             \
    p1 = f[(S)+1] + f[(S)+4] + f[(S)+7] + f[(S)+10] + f[(S)+13];             \
    p2 = f[(S)+2] + f[(S)+5] + f[(S)+8] + f[(S)+11] + f[(S)+14];

// Load one window's chunks (4 or 5 aligned float4) and return pooled means.
// Fast path for fully-interior windows; scalar masked-mean slow path at edges.
__device__ __forceinline__ void gather_pool(
    const float* __restrict__ xb, int id, float& p0, float& p1, float& p2)
{
    if (id >= 2 && id <= T_ - 7) {
        const size_t f0 = (size_t)(id - 2) * 3;          // first valid float
        const int    sh = (int)(f0 & 3);
        const float4* p4 = reinterpret_cast<const float4*>(xb + (f0 & ~(size_t)3));
        float4 c0 = p4[0], c1 = p4[1], c2 = p4[2], c3 = p4[3];
        float4 c4 = make_float4(0.f, 0.f, 0.f, 0.f);
        if (sh >= 2) c4 = p4[4];                          // predicated 5th chunk
        float f[20] = { c0.x, c0.y, c0.z, c0.w,
                        c1.x, c1.y, c1.z, c1.w,
                        c2.x, c2.y, c2.z, c2.w,
                        c3.x, c3.y, c3.z, c3.w,
                        c4.x, c4.y, c4.z, c4.w };
        switch (sh) {
            case 0:  { POOL3(f, 0, p0, p1, p2) } break;
            case 1:  { POOL3(f, 1, p0, p1, p2) } break;
            case 2:  { POOL3(f, 2, p0, p1, p2) } break;
            default: { POOL3(f, 3, p0, p1, p2) } break;
        }
        p0 *= 0.2f; p1 *= 0.2f; p2 *= 0.2f;
    } else {
        float s0 = 0.f, s1 = 0.f, s2 = 0.f, cnt = 0.f;
        #pragma unroll
        for (int o = -2; o <= 2; o++) {
            int pos = id + o;
            if (pos >= 0 && pos < T_) {
                const float* r = xb + (size_t)pos * 3;
                s0 += r[0]; s1 += r[1]; s2 += r[2]; cnt += 1.0f;
            }
        }
        const float inv = 1.0f / cnt;
        p0 = s0 * inv; p1 = s1 * inv; p2 = s2 * inv;
    }
}

__global__ __launch_bounds__(256, 4) void refiner_kernel(
    const float* __restrict__ x,          // [B, T, C]
    const int*   __restrict__ ids,        // [B, K] int32
    const float* __restrict__ W1,         // [C, H]
    const float* __restrict__ b1,         // [H]
    const float* __restrict__ W2,         // [H, 1]
    const float* __restrict__ b2,         // [1]
    float* __restrict__ out)              // [B, K]
{
    __shared__ __align__(16) float sW1[C_ * H_];
    __shared__ __align__(16) float sB1[H_];
    __shared__ __align__(16) float sW2[H_];
    __shared__ float sB2;

    const int tid = threadIdx.x;
    if (tid < 96)        sW1[tid]       = W1[tid];
    else if (tid < 128)  sB1[tid - 96]  = b1[tid - 96];
    else if (tid < 160)  sW2[tid - 128] = W2[tid - 128];
    else if (tid == 160) sB2            = b2[0];
    __syncthreads();

    // Each thread handles 2 consecutive windows (never straddles a batch:
    // batch boundaries are multiples of K=16384, even).
    const int t    = blockIdx.x * 256 + tid;      // 0 .. B*K/2-1
    const int gid0 = t * 2;
    const int b    = gid0 >> 14;
    const int2 idp = reinterpret_cast<const int2*>(ids)[t];   // coalesced 8B
    const float* xb = x + (size_t)b * ((size_t)T_ * C_);

    float a0, a1, a2, q0, q1, q2;
    gather_pool(xb, idp.x, a0, a1, a2);
    gather_pool(xb, idp.y, q0, q1, q2);

    // Fused MLP for both windows: weights LDS'd once.
    float accA = sB2, accB = sB2;
    const float4* wA = reinterpret_cast<const float4*>(sW1);        // c=0
    const float4* wB = reinterpret_cast<const float4*>(sW1 + 32);   // c=1
    const float4* wC = reinterpret_cast<const float4*>(sW1 + 64);   // c=2
    const float4* vb = reinterpret_cast<const float4*>(sB1);
    const float4* v2 = reinterpret_cast<const float4*>(sW2);
    #pragma unroll
    for (int j = 0; j < H_ / 4; j++) {
        float4 wa = wA[j], wb_ = wB[j], wc = wC[j], dd = vb[j], ee = v2[j];
        float h;
        h = fmaf(a0, wa.x, fmaf(a1, wb_.x, fmaf(a2, wc.x, dd.x)));
        accA = fmaf(fmaxf(h, 0.f), ee.x, accA);
        h = fmaf(q0, wa.x, fmaf(q1, wb_.x, fmaf(q2, wc.x, dd.x)));
        accB = fmaf(fmaxf(h, 0.f), ee.x, accB);
        h = fmaf(a0, wa.y, fmaf(a1, wb_.y, fmaf(a2, wc.y, dd.y)));
        accA = fmaf(fmaxf(h, 0.f), ee.y, accA);
        h = fmaf(q0, wa.y, fmaf(q1, wb_.y, fmaf(q2, wc.y, dd.y)));
        accB = fmaf(fmaxf(h, 0.f), ee.y, accB);
        h = fmaf(a0, wa.z, fmaf(a1, wb_.z, fmaf(a2, wc.z, dd.z)));
        accA = fmaf(fmaxf(h, 0.f), ee.z, accA);
        h = fmaf(q0, wa.z, fmaf(q1, wb_.z, fmaf(q2, wc.z, dd.z)));
        accB = fmaf(fmaxf(h, 0.f), ee.z, accB);
        h = fmaf(a0, wa.w, fmaf(a1, wb_.w, fmaf(a2, wc.w, dd.w)));
        accA = fmaf(fmaxf(h, 0.f), ee.w, accA);
        h = fmaf(q0, wa.w, fmaf(q1, wb_.w, fmaf(q2, wc.w, dd.w)));
        accB = fmaf(fmaxf(h, 0.f), ee.w, accB);
    }

    reinterpret_cast<float2*>(out)[t] = make_float2(accA, accB);   // coalesced
}

extern "C" void kernel_launch(void* const* d_in, const int* in_sizes, int n_in,
                              void* d_out, int out_size) {
    const float* x   = (const float*)d_in[0];
    const int*   ids = (const int*)d_in[1];
    const float* W1  = (const float*)d_in[2];
    const float* b1  = (const float*)d_in[3];
    const float* W2  = (const float*)d_in[4];
    const float* b2  = (const float*)d_in[5];
    float*       out = (float*)d_out;

    const int total   = out_size;           // B*K = 1048576
    const int threads = total / 2;          // 2 windows per thread
    const int block   = 256;
    const int grid    = threads / block;    // 2048
    refiner_kernel<<<grid, block>>>(x, ids, W1, b1, W2, b2, out);
}

// round 4
// speedup vs baseline: 1.0156x; 1.0135x over previous
#include <cuda_runtime.h>
#include <cuda_bf16.h>

#define B_  64
#define T_  262144
#define C_  3
#define K_  16384
#define H_  32

#define POOL3(f, S, p0, p1, p2)                                              \
    p0 = f[(S)+0] + f[(S)+3] + f[(S)+6] + f[(S)+9]  + f[(S)+12];             \
    p1 = f[(S)+1] + f[(S)+4] + f[(S)+7] + f[(S)+10] + f[(S)+13];             \
    p2 = f[(S)+2] + f[(S)+5] + f[(S)+8] + f[(S)+11] + f[(S)+14];

// Load one window (4 or 5 aligned float4, sector-exact) and pool to means.
__device__ __forceinline__ void gather_pool(
    const float* __restrict__ xb, int id, float& p0, float& p1, float& p2)
{
    if (id >= 2 && id <= T_ - 7) {
        const size_t f0 = (size_t)(id - 2) * 3;          // first valid float
        const int    sh = (int)(f0 & 3);
        const float4* p4 = reinterpret_cast<const float4*>(xb + (f0 & ~(size_t)3));
        float4 c0 = __ldcg(p4 + 0);
        float4 c1 = __ldcg(p4 + 1);
        float4 c2 = __ldcg(p4 + 2);
        float4 c3 = __ldcg(p4 + 3);
        float4 c4 = make_float4(0.f, 0.f, 0.f, 0.f);
        if (sh >= 2) c4 = __ldcg(p4 + 4);                // predicated 5th chunk
        float f[20] = { c0.x, c0.y, c0.z, c0.w,
                        c1.x, c1.y, c1.z, c1.w,
                        c2.x, c2.y, c2.z, c2.w,
                        c3.x, c3.y, c3.z, c3.w,
                        c4.x, c4.y, c4.z, c4.w };
        switch (sh) {
            case 0:  { POOL3(f, 0, p0, p1, p2) } break;
            case 1:  { POOL3(f, 1, p0, p1, p2) } break;
            case 2:  { POOL3(f, 2, p0, p1, p2) } break;
            default: { POOL3(f, 3, p0, p1, p2) } break;
        }
        p0 *= 0.2f; p1 *= 0.2f; p2 *= 0.2f;
    } else {
        // Edge windows (~70 total of 1M): scalar masked mean.
        float s0 = 0.f, s1 = 0.f, s2 = 0.f, cnt = 0.f;
        #pragma unroll
        for (int o = -2; o <= 2; o++) {
            int pos = id + o;
            if (pos >= 0 && pos < T_) {
                const float* r = xb + (size_t)pos * 3;
                s0 += r[0]; s1 += r[1]; s2 += r[2]; cnt += 1.0f;
            }
        }
        const float inv = 1.0f / cnt;
        p0 = s0 * inv; p1 = s1 * inv; p2 = s2 * inv;
    }
}

__global__ __launch_bounds__(256, 6) void refiner_kernel(
    const float* __restrict__ x,          // [B, T, C]
    const int*   __restrict__ ids,        // [B, K] int32
    const float* __restrict__ W1,         // [C, H]
    const float* __restrict__ b1,         // [H]
    const float* __restrict__ W2,         // [H, 1]
    const float* __restrict__ b2,         // [1]
    float* __restrict__ out)              // [B, K]
{
    __shared__ __align__(16) float sW1[C_ * H_];
    __shared__ __align__(16) float sB1[H_];
    __shared__ __align__(16) float sW2[H_];
    __shared__ float sB2;

    const int tid = threadIdx.x;
    if (tid < 96)        sW1[tid]       = W1[tid];
    else if (tid < 128)  sB1[tid - 96]  = b1[tid - 96];
    else if (tid < 160)  sW2[tid - 128] = W2[tid - 128];
    else if (tid == 160) sB2            = b2[0];
    __syncthreads();

    // 2 consecutive windows per thread (never straddles a batch: K even).
    const int t    = blockIdx.x * 256 + tid;      // 0 .. B*K/2-1
    const int gid0 = t * 2;
    const int b    = gid0 >> 14;
    const int2 idp = reinterpret_cast<const int2*>(ids)[t];
    const float* xb = x + (size_t)b * ((size_t)T_ * C_);

    float a0, a1, a2, q0, q1, q2;
    gather_pool(xb, idp.x, a0, a1, a2);
    gather_pool(xb, idp.y, q0, q1, q2);

    // Fused MLP for both windows: weights LDS'd once.
    float accA = sB2, accB = sB2;
    const float4* wA = reinterpret_cast<const float4*>(sW1);        // c=0
    const float4* wB = reinterpret_cast<const float4*>(sW1 + 32);   // c=1
    const float4* wC = reinterpret_cast<const float4*>(sW1 + 64);   // c=2
    const float4* vb = reinterpret_cast<const float4*>(sB1);
    const float4* v2 = reinterpret_cast<const float4*>(sW2);
    #pragma unroll
    for (int j = 0; j < H_ / 4; j++) {
        float4 wa = wA[j], wb_ = wB[j], wc = wC[j], dd = vb[j], ee = v2[j];
        float h;
        h = fmaf(a0, wa.x, fmaf(a1, wb_.x, fmaf(a2, wc.x, dd.x)));
        accA = fmaf(fmaxf(h, 0.f), ee.x, accA);
        h = fmaf(q0, wa.x, fmaf(q1, wb_.x, fmaf(q2, wc.x, dd.x)));
        accB = fmaf(fmaxf(h, 0.f), ee.x, accB);
        h = fmaf(a0, wa.y, fmaf(a1, wb_.y, fmaf(a2, wc.y, dd.y)));
        accA = fmaf(fmaxf(h, 0.f), ee.y, accA);
        h = fmaf(q0, wa.y, fmaf(q1, wb_.y, fmaf(q2, wc.y, dd.y)));
        accB = fmaf(fmaxf(h, 0.f), ee.y, accB);
        h = fmaf(a0, wa.z, fmaf(a1, wb_.z, fmaf(a2, wc.z, dd.z)));
        accA = fmaf(fmaxf(h, 0.f), ee.z, accA);
        h = fmaf(q0, wa.z, fmaf(q1, wb_.z, fmaf(q2, wc.z, dd.z)));
        accB = fmaf(fmaxf(h, 0.f), ee.z, accB);
        h = fmaf(a0, wa.w, fmaf(a1, wb_.w, fmaf(a2, wc.w, dd.w)));
        accA = fmaf(fmaxf(h, 0.f), ee.w, accA);
        h = fmaf(q0, wa.w, fmaf(q1, wb_.w, fmaf(q2, wc.w, dd.w)));
        accB = fmaf(fmaxf(h, 0.f), ee.w, accB);
    }

    reinterpret_cast<float2*>(out)[t] = make_float2(accA, accB);
}

extern "C" void kernel_launch(void* const* d_in, const int* in_sizes, int n_in,
                              void* d_out, int out_size) {
    const float* x   = (const float*)d_in[0];
    const int*   ids = (const int*)d_in[1];
    const float* W1  = (const float*)d_in[2];
    const float* b1  = (const float*)d_in[3];
    const float* W2  = (const float*)d_in[4];
    const float* b2  = (const float*)d_in[5];
    float*       out = (float*)d_out;

    const int total   = out_size;           // B*K = 1048576
    const int threads = total / 2;          // 2 windows per thread
    const int block   = 256;
    const int grid    = threads / block;    // 2048
    refiner_kernel<<<grid, block>>>(x, ids, W1, b1, W2, b2, out);
}

// round 5
// speedup vs baseline: 1.0724x; 1.0560x over previous
#include <cuda_runtime.h>
#include <cuda_bf16.h>

#define B_  64
#define T_  262144
#define C_  3
#define K_  16384
#define H_  32

#define NSM_      148
#define CTAS_SM_  6
#define BLOCK_    256

#define POOL3(f, S, p0, p1, p2)                                              \
    p0 = f[(S)+0] + f[(S)+3] + f[(S)+6] + f[(S)+9]  + f[(S)+12];             \
    p1 = f[(S)+1] + f[(S)+4] + f[(S)+7] + f[(S)+10] + f[(S)+13];             \
    p2 = f[(S)+2] + f[(S)+5] + f[(S)+8] + f[(S)+11] + f[(S)+14];

// Load one window (4 or 5 aligned float4, sector-exact) and pool to means.
__device__ __forceinline__ void gather_pool(
    const float* __restrict__ xb, int id, float& p0, float& p1, float& p2)
{
    if (id >= 2 && id <= T_ - 7) {
        const size_t f0 = (size_t)(id - 2) * 3;          // first valid float
        const int    sh = (int)(f0 & 3);
        const float4* p4 = reinterpret_cast<const float4*>(xb + (f0 & ~(size_t)3));
        float4 c0 = __ldcg(p4 + 0);
        float4 c1 = __ldcg(p4 + 1);
        float4 c2 = __ldcg(p4 + 2);
        float4 c3 = __ldcg(p4 + 3);
        float4 c4 = make_float4(0.f, 0.f, 0.f, 0.f);
        if (sh >= 2) c4 = __ldcg(p4 + 4);                // predicated 5th chunk
        float f[20] = { c0.x, c0.y, c0.z, c0.w,
                        c1.x, c1.y, c1.z, c1.w,
                        c2.x, c2.y, c2.z, c2.w,
                        c3.x, c3.y, c3.z, c3.w,
                        c4.x, c4.y, c4.z, c4.w };
        switch (sh) {
            case 0:  { POOL3(f, 0, p0, p1, p2) } break;
            case 1:  { POOL3(f, 1, p0, p1, p2) } break;
            case 2:  { POOL3(f, 2, p0, p1, p2) } break;
            default: { POOL3(f, 3, p0, p1, p2) } break;
        }
        p0 *= 0.2f; p1 *= 0.2f; p2 *= 0.2f;
    } else {
        // Edge windows (~70 of 1M): scalar masked mean.
        float s0 = 0.f, s1 = 0.f, s2 = 0.f, cnt = 0.f;
        #pragma unroll
        for (int o = -2; o <= 2; o++) {
            int pos = id + o;
            if (pos >= 0 && pos < T_) {
                const float* r = xb + (size_t)pos * 3;
                s0 += r[0]; s1 += r[1]; s2 += r[2]; cnt += 1.0f;
            }
        }
        const float inv = 1.0f / cnt;
        p0 = s0 * inv; p1 = s1 * inv; p2 = s2 * inv;
    }
}

__global__ __launch_bounds__(BLOCK_, CTAS_SM_) void refiner_kernel(
    const float* __restrict__ x,          // [B, T, C]
    const int*   __restrict__ ids,        // [B, K] int32
    const float* __restrict__ W1,         // [C, H]
    const float* __restrict__ b1,         // [H]
    const float* __restrict__ W2,         // [H, 1]
    const float* __restrict__ b2,         // [1]
    float* __restrict__ out)              // [B, K]
{
    __shared__ __align__(16) float sW1[C_ * H_];
    __shared__ __align__(16) float sB1[H_];
    __shared__ __align__(16) float sW2[H_];
    __shared__ float sB2;

    const int tid = threadIdx.x;
    if (tid < 96)        sW1[tid]       = W1[tid];
    else if (tid < 128)  sB1[tid - 96]  = b1[tid - 96];
    else if (tid < 160)  sW2[tid - 128] = W2[tid - 128];
    else if (tid == 160) sB2            = b2[0];
    __syncthreads();

    const float4* wA = reinterpret_cast<const float4*>(sW1);        // c=0
    const float4* wB = reinterpret_cast<const float4*>(sW1 + 32);   // c=1
    const float4* wC = reinterpret_cast<const float4*>(sW1 + 64);   // c=2
    const float4* vb = reinterpret_cast<const float4*>(sB1);
    const float4* v2 = reinterpret_cast<const float4*>(sW2);
    const int2* ids2 = reinterpret_cast<const int2*>(ids);

    const int NT     = (B_ * K_) / 2;                 // 524288 work items
    const int stride = gridDim.x * BLOCK_;            // 227328
    int t = blockIdx.x * BLOCK_ + tid;

    // Software-pipelined grid-stride loop: prefetch next ids during MLP.
    int2 idp = ids2[t];
    for (;;) {
        const int nt   = t + stride;
        const bool more = (nt < NT);

        const int b = t >> 13;                         // (t*2)/K
        const float* xb = x + (size_t)b * ((size_t)T_ * C_);

        float a0, a1, a2, q0, q1, q2;
        gather_pool(xb, idp.x, a0, a1, a2);
        gather_pool(xb, idp.y, q0, q1, q2);

        int2 nidp;
        if (more) nidp = ids2[nt];                     // prefetch next iter's ids

        float accA = sB2, accB = sB2;
        #pragma unroll
        for (int j = 0; j < H_ / 4; j++) {
            float4 wa = wA[j], wb_ = wB[j], wc = wC[j], dd = vb[j], ee = v2[j];
            float h;
            h = fmaf(a0, wa.x, fmaf(a1, wb_.x, fmaf(a2, wc.x, dd.x)));
            accA = fmaf(fmaxf(h, 0.f), ee.x, accA);
            h = fmaf(q0, wa.x, fmaf(q1, wb_.x, fmaf(q2, wc.x, dd.x)));
            accB = fmaf(fmaxf(h, 0.f), ee.x, accB);
            h = fmaf(a0, wa.y, fmaf(a1, wb_.y, fmaf(a2, wc.y, dd.y)));
            accA = fmaf(fmaxf(h, 0.f), ee.y, accA);
            h = fmaf(q0, wa.y, fmaf(q1, wb_.y, fmaf(q2, wc.y, dd.y)));
            accB = fmaf(fmaxf(h, 0.f), ee.y, accB);
            h = fmaf(a0, wa.z, fmaf(a1, wb_.z, fmaf(a2, wc.z, dd.z)));
            accA = fmaf(fmaxf(h, 0.f), ee.z, accA);
            h = fmaf(q0, wa.z, fmaf(q1, wb_.z, fmaf(q2, wc.z, dd.z)));
            accB = fmaf(fmaxf(h, 0.f), ee.z, accB);
            h = fmaf(a0, wa.w, fmaf(a1, wb_.w, fmaf(a2, wc.w, dd.w)));
            accA = fmaf(fmaxf(h, 0.f), ee.w, accA);
            h = fmaf(q0, wa.w, fmaf(q1, wb_.w, fmaf(q2, wc.w, dd.w)));
            accB = fmaf(fmaxf(h, 0.f), ee.w, accB);
        }

        reinterpret_cast<float2*>(out)[t] = make_float2(accA, accB);

        if (!more) break;
        t = nt;
        idp = nidp;
    }
}

extern "C" void kernel_launch(void* const* d_in, const int* in_sizes, int n_in,
                              void* d_out, int out_size) {
    const float* x   = (const float*)d_in[0];
    const int*   ids = (const int*)d_in[1];
    const float* W1  = (const float*)d_in[2];
    const float* b1  = (const float*)d_in[3];
    const float* W2  = (const float*)d_in[4];
    const float* b2  = (const float*)d_in[5];
    float*       out = (float*)d_out;

    const int grid = NSM_ * CTAS_SM_;        // 888 persistent CTAs
    refiner_kernel<<<grid, BLOCK_>>>(x, ids, W1, b1, W2, b2, out);
}